// round 1
// baseline (speedup 1.0000x reference)
#include <cuda_runtime.h>
#include <cuda_bf16.h>
#include <cstdint>

#define BATCH 8
#define HW    4096
#define CIN   256
#define DQK   128
#define DV    256

// ---------------- scratch (static __device__, no allocs) ----------------
__device__ __nv_bfloat16 g_Q[(size_t)BATCH * HW * DQK];   // [b][n][d]
__device__ __nv_bfloat16 g_K[(size_t)BATCH * HW * DQK];   // [b][n][d]
__device__ __nv_bfloat16 g_V[(size_t)BATCH * HW * DV];    // [b][n][e]
__device__ float         g_H[(size_t)BATCH * HW * DV];    // [b][n][e]

// ---------------- helpers ----------------
__device__ __forceinline__ uint32_t smem_u32(const void* p) {
    return (uint32_t)__cvta_generic_to_shared(p);
}
__device__ __forceinline__ void ldm_x4(uint32_t& r0, uint32_t& r1, uint32_t& r2, uint32_t& r3, uint32_t addr) {
    asm volatile("ldmatrix.sync.aligned.m8n8.x4.shared.b16 {%0,%1,%2,%3},[%4];"
                 : "=r"(r0), "=r"(r1), "=r"(r2), "=r"(r3) : "r"(addr));
}
__device__ __forceinline__ void ldm_x2(uint32_t& r0, uint32_t& r1, uint32_t addr) {
    asm volatile("ldmatrix.sync.aligned.m8n8.x2.shared.b16 {%0,%1},[%2];"
                 : "=r"(r0), "=r"(r1) : "r"(addr));
}
__device__ __forceinline__ void ldm_x2t(uint32_t& r0, uint32_t& r1, uint32_t addr) {
    asm volatile("ldmatrix.sync.aligned.m8n8.x2.trans.shared.b16 {%0,%1},[%2];"
                 : "=r"(r0), "=r"(r1) : "r"(addr));
}
__device__ __forceinline__ void mma_bf16(float& c0, float& c1, float& c2, float& c3,
                                         uint32_t a0, uint32_t a1, uint32_t a2, uint32_t a3,
                                         uint32_t b0, uint32_t b1) {
    asm volatile("mma.sync.aligned.m16n8k16.row.col.f32.bf16.bf16.f32 "
                 "{%0,%1,%2,%3},{%4,%5,%6,%7},{%8,%9},{%0,%1,%2,%3};"
                 : "+f"(c0), "+f"(c1), "+f"(c2), "+f"(c3)
                 : "r"(a0), "r"(a1), "r"(a2), "r"(a3), "r"(b0), "r"(b1));
}
__device__ __forceinline__ uint32_t packbf2(float lo, float hi) {
    __nv_bfloat162 v = __floats2bfloat162_rn(lo, hi);
    return *reinterpret_cast<uint32_t*>(&v);
}
__device__ __forceinline__ void fma16v(float acc[16], float wq, const float* __restrict__ row) {
    const float4* r4 = reinterpret_cast<const float4*>(row);
    float4 h0 = r4[0], h1 = r4[1], h2 = r4[2], h3 = r4[3];
    acc[0]  += wq * h0.x; acc[1]  += wq * h0.y; acc[2]  += wq * h0.z; acc[3]  += wq * h0.w;
    acc[4]  += wq * h1.x; acc[5]  += wq * h1.y; acc[6]  += wq * h1.z; acc[7]  += wq * h1.w;
    acc[8]  += wq * h2.x; acc[9]  += wq * h2.y; acc[10] += wq * h2.z; acc[11] += wq * h2.w;
    acc[12] += wq * h3.x; acc[13] += wq * h3.y; acc[14] += wq * h3.z; acc[15] += wq * h3.w;
}

// ---------------- projection: Q = yf*Wq^T, K = xf*Wk^T, V = xf*Wv^T ----------------
__global__ __launch_bounds__(256) void proj_kernel(
        const float* __restrict__ x, const float* __restrict__ y,
        const float* __restrict__ Wq, const float* __restrict__ bq,
        const float* __restrict__ Wk, const float* __restrict__ bk,
        const float* __restrict__ Wv, const float* __restrict__ bv) {
    __shared__ float xs[CIN][16];
    __shared__ float ys[CIN][16];
    const int b = blockIdx.y, n0 = blockIdx.x * 16, tid = threadIdx.x;
    const float* xb = x + (size_t)b * CIN * HW;
    const float* yb = y + (size_t)b * CIN * HW;
    for (int i = tid; i < CIN * 16; i += 256) {
        int n = i & 15, c = i >> 4;
        xs[c][n] = xb[c * HW + n0 + n];
        ys[c][n] = yb[c * HW + n0 + n];
    }
    __syncthreads();
    #pragma unroll
    for (int half = 0; half < 2; half++) {
        const int o = tid + half * 256;
        const float* Wrow; float bias; const float (*A)[16];
        if (o < 128)      { Wrow = Wq + o * CIN;         bias = bq[o];       A = ys; }
        else if (o < 256) { Wrow = Wk + (o - 128) * CIN; bias = bk[o - 128]; A = xs; }
        else              { Wrow = Wv + (o - 256) * CIN; bias = bv[o - 256]; A = xs; }
        float acc[16];
        #pragma unroll
        for (int n = 0; n < 16; n++) acc[n] = 0.f;
        for (int c = 0; c < CIN; c += 4) {
            float4 w = *reinterpret_cast<const float4*>(Wrow + c);
            fma16v(acc, w.x, A[c]);
            fma16v(acc, w.y, A[c + 1]);
            fma16v(acc, w.z, A[c + 2]);
            fma16v(acc, w.w, A[c + 3]);
        }
        __nv_bfloat16* dst; int stride;
        if (o < 128)      { dst = g_Q + ((size_t)b * HW + n0) * DQK + o;         stride = DQK; }
        else if (o < 256) { dst = g_K + ((size_t)b * HW + n0) * DQK + (o - 128); stride = DQK; }
        else              { dst = g_V + ((size_t)b * HW + n0) * DV  + (o - 256); stride = DV;  }
        #pragma unroll
        for (int n = 0; n < 16; n++) dst[n * stride] = __float2bfloat16(acc[n] + bias);
    }
}

// ---------------- flash attention (mma.sync bf16) ----------------
// BM=128 (8 warps x 16 rows), BN=64, D=128, DV=256
#define SQ_STRIDE 136   // 128 + 8 pad (bf16 elems)
#define SV_STRIDE 264   // 256 + 8 pad
#define SMEM_BF16_ELEMS (128 * SQ_STRIDE + 64 * SQ_STRIDE + 64 * SV_STRIDE)  // 43008
#define FLASH_SMEM_BYTES (SMEM_BF16_ELEMS * 2)                                // 86016

__global__ __launch_bounds__(256, 1) void flash_kernel() {
    extern __shared__ __nv_bfloat16 smem[];
    __nv_bfloat16* sQ = smem;
    __nv_bfloat16* sK = smem + 128 * SQ_STRIDE;
    __nv_bfloat16* sV = smem + 128 * SQ_STRIDE + 64 * SQ_STRIDE;

    const int b = blockIdx.y;
    const int q0 = blockIdx.x * 128;
    const int tid = threadIdx.x, warp = tid >> 5, lane = tid & 31;
    const __nv_bfloat16* Qg = g_Q + (size_t)b * HW * DQK;
    const __nv_bfloat16* Kg = g_K + (size_t)b * HW * DQK;
    const __nv_bfloat16* Vg = g_V + (size_t)b * HW * DV;

    // stage Q tile once
    for (int i = tid; i < 128 * 16; i += 256) {
        int r = i >> 4, d8 = (i & 15) << 3;
        *reinterpret_cast<uint4*>(sQ + r * SQ_STRIDE + d8) =
            *reinterpret_cast<const uint4*>(Qg + (size_t)(q0 + r) * DQK + d8);
    }

    float O[32][4];
    #pragma unroll
    for (int n = 0; n < 32; n++) { O[n][0] = O[n][1] = O[n][2] = O[n][3] = 0.f; }
    float m0 = -1e30f, m1 = -1e30f, l0 = 0.f, l1 = 0.f;

    const int mrow0 = warp * 16;
    const uint32_t aQbase = smem_u32(sQ + (mrow0 + (lane & 15)) * SQ_STRIDE + ((lane >> 4) & 1) * 8);
    const int kRowSel = lane & 7;
    const int kColSel = ((lane >> 3) & 1) * 8;
    const float qs = 0.08838834764831845f * 1.4426950408889634f;  // scale * log2(e)

    for (int kv0 = 0; kv0 < HW; kv0 += 64) {
        __syncthreads();
        for (int i = tid; i < 64 * 16; i += 256) {
            int r = i >> 4, d8 = (i & 15) << 3;
            *reinterpret_cast<uint4*>(sK + r * SQ_STRIDE + d8) =
                *reinterpret_cast<const uint4*>(Kg + (size_t)(kv0 + r) * DQK + d8);
        }
        for (int i = tid; i < 64 * 32; i += 256) {
            int r = i >> 5, d8 = (i & 31) << 3;
            *reinterpret_cast<uint4*>(sV + r * SV_STRIDE + d8) =
                *reinterpret_cast<const uint4*>(Vg + (size_t)(kv0 + r) * DV + d8);
        }
        __syncthreads();

        // S = Q K^T  (16x64 per warp)
        float S[8][4];
        #pragma unroll
        for (int j = 0; j < 8; j++) { S[j][0] = S[j][1] = S[j][2] = S[j][3] = 0.f; }
        #pragma unroll
        for (int kk = 0; kk < 8; kk++) {
            uint32_t a0, a1, a2, a3;
            ldm_x4(a0, a1, a2, a3, aQbase + kk * 32);
            #pragma unroll
            for (int j = 0; j < 8; j++) {
                uint32_t b0, b1;
                uint32_t addr = smem_u32(sK + (j * 8 + kRowSel) * SQ_STRIDE + kk * 16 + kColSel);
                ldm_x2(b0, b1, addr);
                mma_bf16(S[j][0], S[j][1], S[j][2], S[j][3], a0, a1, a2, a3, b0, b1);
            }
        }

        // online softmax (rows lane/4 and lane/4+8)
        float mx0 = -1e30f, mx1 = -1e30f;
        #pragma unroll
        for (int j = 0; j < 8; j++) {
            mx0 = fmaxf(mx0, fmaxf(S[j][0], S[j][1]));
            mx1 = fmaxf(mx1, fmaxf(S[j][2], S[j][3]));
        }
        mx0 = fmaxf(mx0, __shfl_xor_sync(0xffffffffu, mx0, 1));
        mx0 = fmaxf(mx0, __shfl_xor_sync(0xffffffffu, mx0, 2));
        mx1 = fmaxf(mx1, __shfl_xor_sync(0xffffffffu, mx1, 1));
        mx1 = fmaxf(mx1, __shfl_xor_sync(0xffffffffu, mx1, 2));
        mx0 *= qs; mx1 *= qs;
        const float mn0 = fmaxf(m0, mx0), mn1 = fmaxf(m1, mx1);
        const float al0 = exp2f(m0 - mn0), al1 = exp2f(m1 - mn1);
        m0 = mn0; m1 = mn1;
        float rs0 = 0.f, rs1 = 0.f;
        #pragma unroll
        for (int j = 0; j < 8; j++) {
            S[j][0] = exp2f(fmaf(S[j][0], qs, -mn0));
            S[j][1] = exp2f(fmaf(S[j][1], qs, -mn0));
            S[j][2] = exp2f(fmaf(S[j][2], qs, -mn1));
            S[j][3] = exp2f(fmaf(S[j][3], qs, -mn1));
            rs0 += S[j][0] + S[j][1];
            rs1 += S[j][2] + S[j][3];
        }
        l0 = l0 * al0 + rs0;
        l1 = l1 * al1 + rs1;
        #pragma unroll
        for (int n = 0; n < 32; n++) {
            O[n][0] *= al0; O[n][1] *= al0; O[n][2] *= al1; O[n][3] *= al1;
        }

        // O += P V   (P stays in registers: S layout == A layout)
        #pragma unroll
        for (int kc = 0; kc < 4; kc++) {
            uint32_t a0 = packbf2(S[2 * kc][0],     S[2 * kc][1]);
            uint32_t a1 = packbf2(S[2 * kc][2],     S[2 * kc][3]);
            uint32_t a2 = packbf2(S[2 * kc + 1][0], S[2 * kc + 1][1]);
            uint32_t a3 = packbf2(S[2 * kc + 1][2], S[2 * kc + 1][3]);
            uint32_t vbase = smem_u32(sV + (kc * 16 + kRowSel + kColSel) * SV_STRIDE);
            #pragma unroll
            for (int n = 0; n < 32; n++) {
                uint32_t b0, b1;
                ldm_x2t(b0, b1, vbase + n * 16);
                mma_bf16(O[n][0], O[n][1], O[n][2], O[n][3], a0, a1, a2, a3, b0, b1);
            }
        }
    }

    // finalize: divide by l, write H
    l0 += __shfl_xor_sync(0xffffffffu, l0, 1);
    l0 += __shfl_xor_sync(0xffffffffu, l0, 2);
    l1 += __shfl_xor_sync(0xffffffffu, l1, 1);
    l1 += __shfl_xor_sync(0xffffffffu, l1, 2);
    const float inv0 = 1.f / l0, inv1 = 1.f / l1;
    const int r0 = q0 + mrow0 + (lane >> 2);
    float* H0 = g_H + ((size_t)b * HW + r0) * DV + (lane & 3) * 2;
    float* H1 = H0 + 8 * DV;
    #pragma unroll
    for (int n = 0; n < 32; n++) {
        *reinterpret_cast<float2*>(H0 + n * 8) = make_float2(O[n][0] * inv0, O[n][1] * inv0);
        *reinterpret_cast<float2*>(H1 + n * 8) = make_float2(O[n][2] * inv1, O[n][3] * inv1);
    }
}

// ---------------- output projection + residual ----------------
__global__ __launch_bounds__(256) void out_kernel(
        const float* __restrict__ x, const float* __restrict__ Wo,
        const float* __restrict__ bo, float* __restrict__ out) {
    __shared__ float hs[DV][16];   // [e][n]
    const int b = blockIdx.y, n0 = blockIdx.x * 16, tid = threadIdx.x;
    const float* Hb = g_H + ((size_t)b * HW + n0) * DV;
    #pragma unroll
    for (int k = 0; k < 16; k++) hs[tid][k] = Hb[k * DV + tid];
    __syncthreads();
    float acc[16];
    #pragma unroll
    for (int n = 0; n < 16; n++) acc[n] = 0.f;
    const float* Wrow = Wo + tid * DV;
    for (int e = 0; e < DV; e += 4) {
        float4 w = *reinterpret_cast<const float4*>(Wrow + e);
        fma16v(acc, w.x, hs[e]);
        fma16v(acc, w.y, hs[e + 1]);
        fma16v(acc, w.z, hs[e + 2]);
        fma16v(acc, w.w, hs[e + 3]);
    }
    const float bias = bo[tid];
    const float* xrow = x + ((size_t)b * CIN + tid) * HW + n0;
    float* orow = out + ((size_t)b * CIN + tid) * HW + n0;
    #pragma unroll
    for (int n4 = 0; n4 < 4; n4++) {
        float4 xv = *reinterpret_cast<const float4*>(xrow + n4 * 4);
        float4 ov = make_float4(xv.x + acc[n4 * 4 + 0] + bias,
                                xv.y + acc[n4 * 4 + 1] + bias,
                                xv.z + acc[n4 * 4 + 2] + bias,
                                xv.w + acc[n4 * 4 + 3] + bias);
        *reinterpret_cast<float4*>(orow + n4 * 4) = ov;
    }
}

// ---------------- launch ----------------
extern "C" void kernel_launch(void* const* d_in, const int* in_sizes, int n_in,
                              void* d_out, int out_size) {
    const float* x  = (const float*)d_in[0];
    const float* y  = (const float*)d_in[1];
    const float* Wq = (const float*)d_in[2];
    const float* bq = (const float*)d_in[3];
    const float* Wk = (const float*)d_in[4];
    const float* bk = (const float*)d_in[5];
    const float* Wv = (const float*)d_in[6];
    const float* bv = (const float*)d_in[7];
    const float* Wo = (const float*)d_in[8];
    const float* bo = (const float*)d_in[9];
    float* out = (float*)d_out;

    proj_kernel<<<dim3(HW / 16, BATCH), 256>>>(x, y, Wq, bq, Wk, bk, Wv, bv);

    cudaFuncSetAttribute(flash_kernel, cudaFuncAttributeMaxDynamicSharedMemorySize, FLASH_SMEM_BYTES);
    flash_kernel<<<dim3(HW / 128, BATCH), 256, FLASH_SMEM_BYTES>>>();

    out_kernel<<<dim3(HW / 16, BATCH), 256>>>(x, Wo, bo, out);
}

// round 2
// speedup vs baseline: 2.5394x; 2.5394x over previous
#include <cuda_runtime.h>
#include <cuda_bf16.h>
#include <cstdint>

#define BATCH 8
#define HW    4096
#define CIN   256
#define DQK   128
#define DV    256

// ---------------- scratch (static __device__, no allocs) ----------------
__device__ __nv_bfloat16 g_Xb[(size_t)BATCH * CIN * HW];     // x in bf16, [b][c][n]
__device__ __nv_bfloat16 g_Yb[(size_t)BATCH * CIN * HW];     // y in bf16
__device__ __nv_bfloat16 g_Wqkv[512 * 256];                  // rows 0-127 Wq, 128-255 Wk, 256-511 Wv
__device__ __nv_bfloat16 g_Wob[256 * 256];                   // Wo bf16
__device__ __nv_bfloat16 g_Q[(size_t)BATCH * HW * DQK];      // [b][n][d]
__device__ __nv_bfloat16 g_K[(size_t)BATCH * HW * DQK];      // [b][n][d]
__device__ __nv_bfloat16 g_V[(size_t)BATCH * HW * DV];       // [b][n][e]
__device__ __nv_bfloat16 g_Hb[(size_t)BATCH * HW * DV];      // attention output, bf16

// ---------------- helpers ----------------
__device__ __forceinline__ uint32_t smem_u32(const void* p) {
    return (uint32_t)__cvta_generic_to_shared(p);
}
__device__ __forceinline__ void ldm_x4(uint32_t& r0, uint32_t& r1, uint32_t& r2, uint32_t& r3, uint32_t addr) {
    asm volatile("ldmatrix.sync.aligned.m8n8.x4.shared.b16 {%0,%1,%2,%3},[%4];"
                 : "=r"(r0), "=r"(r1), "=r"(r2), "=r"(r3) : "r"(addr));
}
__device__ __forceinline__ void ldm_x4t(uint32_t& r0, uint32_t& r1, uint32_t& r2, uint32_t& r3, uint32_t addr) {
    asm volatile("ldmatrix.sync.aligned.m8n8.x4.trans.shared.b16 {%0,%1,%2,%3},[%4];"
                 : "=r"(r0), "=r"(r1), "=r"(r2), "=r"(r3) : "r"(addr));
}
__device__ __forceinline__ void mma_bf16(float& c0, float& c1, float& c2, float& c3,
                                         uint32_t a0, uint32_t a1, uint32_t a2, uint32_t a3,
                                         uint32_t b0, uint32_t b1) {
    asm volatile("mma.sync.aligned.m16n8k16.row.col.f32.bf16.bf16.f32 "
                 "{%0,%1,%2,%3},{%4,%5,%6,%7},{%8,%9},{%0,%1,%2,%3};"
                 : "+f"(c0), "+f"(c1), "+f"(c2), "+f"(c3)
                 : "r"(a0), "r"(a1), "r"(a2), "r"(a3), "r"(b0), "r"(b1));
}
__device__ __forceinline__ uint32_t packbf2(float lo, float hi) {
    __nv_bfloat162 v = __floats2bfloat162_rn(lo, hi);
    return *reinterpret_cast<uint32_t*>(&v);
}
#define CP16(saddr, gptr) \
    asm volatile("cp.async.cg.shared.global [%0],[%1],16;" :: "r"(saddr), "l"(gptr))
#define CP_COMMIT() asm volatile("cp.async.commit_group;")
#define CP_WAIT1()  asm volatile("cp.async.wait_group 1;")
#define CP_WAIT0()  asm volatile("cp.async.wait_group 0;")

// ---------------- prep: fp32 -> bf16 conversion ----------------
__global__ __launch_bounds__(256) void cvt_kernel(const float* __restrict__ src,
                                                  __nv_bfloat16* __restrict__ dst, int n) {
    int i = (blockIdx.x * 256 + threadIdx.x) * 4;
    if (i < n) {
        float4 v = *reinterpret_cast<const float4*>(src + i);
        uint2 o;
        o.x = packbf2(v.x, v.y);
        o.y = packbf2(v.z, v.w);
        *reinterpret_cast<uint2*>(dst + i) = o;
    }
}

// ---------------- projection GEMM (tensor cores) ----------------
// Per CTA: 64 spatial rows x 512 outputs, K=256 chunked by 64.
// 8 warps = 4 (m-groups of 16 rows) x 2 (output halves of 256).
#define PSTR 72
#define PROJ_SMEM ((128 * PSTR + 512 * PSTR) * 2)   // sX+sY + sW = 92160 B

__global__ __launch_bounds__(256, 1) void proj_mma_kernel(
        const float* __restrict__ bq, const float* __restrict__ bk, const float* __restrict__ bv) {
    extern __shared__ __nv_bfloat16 psmem[];
    __nv_bfloat16* sX = psmem;                 // [64][72]
    __nv_bfloat16* sY = psmem + 64 * PSTR;     // [64][72]
    __nv_bfloat16* sW = psmem + 128 * PSTR;    // [512][72]
    __shared__ float sBias[512];

    const int b = blockIdx.y, n0 = blockIdx.x * 64;
    const int tid = threadIdx.x, warp = tid >> 5, lane = tid & 31;
    const int mg = warp & 3, dg = warp >> 2;

    for (int i = tid; i < 512; i += 256)
        sBias[i] = (i < 128) ? bq[i] : (i < 256) ? bk[i - 128] : bv[i - 256];

    const __nv_bfloat16* Xb = g_Xb + (size_t)b * CIN * HW + n0;
    const __nv_bfloat16* Yb = g_Yb + (size_t)b * CIN * HW + n0;

    float acc[32][4];
    #pragma unroll
    for (int t = 0; t < 32; t++) { acc[t][0] = acc[t][1] = acc[t][2] = acc[t][3] = 0.f; }

    // A (trans) addressing: row = k-within-chunk, col = m
    const int arow = (lane & 7) + ((lane >> 4) & 1) * 8;
    const int acol = mg * 16 + ((lane >> 3) & 1) * 8;
    const uint32_t aXbase = smem_u32(sX + arow * PSTR + acol);
    const uint32_t aYbase = smem_u32(sY + arow * PSTR + acol);
    // B addressing: row = output d, col = k-within-chunk
    const int brow = (lane & 7) + ((lane >> 4) & 1) * 8;
    const int bcol = ((lane >> 3) & 1) * 8;
    const uint32_t bWbase = smem_u32(sW + (dg * 256 + brow) * PSTR + bcol);

    for (int ck = 0; ck < 4; ck++) {
        __syncthreads();
        #pragma unroll
        for (int j = 0; j < 4; j++) {
            int u = tid + j * 256;              // 0..1023
            int r = u >> 3, c8 = (u & 7) * 8;
            *reinterpret_cast<uint4*>(sX + r * PSTR + c8) =
                *reinterpret_cast<const uint4*>(Xb + (size_t)(ck * 64 + r) * HW + c8);
            *reinterpret_cast<uint4*>(sY + r * PSTR + c8) =
                *reinterpret_cast<const uint4*>(Yb + (size_t)(ck * 64 + r) * HW + c8);
        }
        #pragma unroll
        for (int j = 0; j < 16; j++) {
            int u = tid + j * 256;              // 0..4095
            int r = u >> 3, c8 = (u & 7) * 8;
            *reinterpret_cast<uint4*>(sW + r * PSTR + c8) =
                *reinterpret_cast<const uint4*>(g_Wqkv + (size_t)r * 256 + ck * 64 + c8);
        }
        __syncthreads();

        #pragma unroll
        for (int kk = 0; kk < 4; kk++) {
            uint32_t ax0, ax1, ax2, ax3;
            ldm_x4t(ax0, ax1, ax2, ax3, aXbase + kk * 16 * PSTR * 2);
            uint32_t ay0 = ax0, ay1 = ax1, ay2 = ax2, ay3 = ax3;
            if (dg == 0) ldm_x4t(ay0, ay1, ay2, ay3, aYbase + kk * 16 * PSTR * 2);
            #pragma unroll
            for (int t2 = 0; t2 < 16; t2++) {
                uint32_t b0, b1, b2, b3;
                ldm_x4(b0, b1, b2, b3, bWbase + (t2 * 16 * PSTR + kk * 16) * 2);
                if (dg == 0 && t2 < 8) {   // Q tiles use Y
                    mma_bf16(acc[2*t2][0],   acc[2*t2][1],   acc[2*t2][2],   acc[2*t2][3],   ay0, ay1, ay2, ay3, b0, b1);
                    mma_bf16(acc[2*t2+1][0], acc[2*t2+1][1], acc[2*t2+1][2], acc[2*t2+1][3], ay0, ay1, ay2, ay3, b2, b3);
                } else {                    // K,V tiles use X
                    mma_bf16(acc[2*t2][0],   acc[2*t2][1],   acc[2*t2][2],   acc[2*t2][3],   ax0, ax1, ax2, ax3, b0, b1);
                    mma_bf16(acc[2*t2+1][0], acc[2*t2+1][1], acc[2*t2+1][2], acc[2*t2+1][3], ax0, ax1, ax2, ax3, b2, b3);
                }
            }
        }
    }

    // epilogue: bias + pack bf16 + store to Q/K/V
    const int r = n0 + mg * 16 + (lane >> 2);
    const int cpair = (lane & 3) * 2;
    #pragma unroll
    for (int t = 0; t < 32; t++) {
        int d0 = dg * 256 + t * 8 + cpair;
        float bv0 = sBias[d0], bv1 = sBias[d0 + 1];
        uint32_t v0 = packbf2(acc[t][0] + bv0, acc[t][1] + bv1);
        uint32_t v1 = packbf2(acc[t][2] + bv0, acc[t][3] + bv1);
        __nv_bfloat16* dst; int ld, stride;
        if (d0 < 128)      { dst = g_Q; ld = d0;       stride = DQK; }
        else if (d0 < 256) { dst = g_K; ld = d0 - 128; stride = DQK; }
        else               { dst = g_V; ld = d0 - 256; stride = DV;  }
        *reinterpret_cast<uint32_t*>(dst + ((size_t)b * HW + r) * stride + ld) = v0;
        *reinterpret_cast<uint32_t*>(dst + ((size_t)b * HW + r + 8) * stride + ld) = v1;
    }
}

// ---------------- flash attention (mma.sync bf16, cp.async pipelined) ----------------
#define SQ_STRIDE 136
#define SV_STRIDE 264
#define FLASH_SMEM ((128 * SQ_STRIDE + 2 * 64 * SQ_STRIDE + 2 * 64 * SV_STRIDE) * 2)  // 137216

__global__ __launch_bounds__(256, 1) void flash_kernel() {
    extern __shared__ __nv_bfloat16 smem[];
    __nv_bfloat16* sQ = smem;
    __nv_bfloat16* sK = smem + 128 * SQ_STRIDE;
    __nv_bfloat16* sV = smem + 128 * SQ_STRIDE + 2 * 64 * SQ_STRIDE;

    const int b = blockIdx.y;
    const int q0 = blockIdx.x * 128;
    const int tid = threadIdx.x, warp = tid >> 5, lane = tid & 31;
    const __nv_bfloat16* Qg = g_Q + (size_t)b * HW * DQK;
    const __nv_bfloat16* Kg = g_K + (size_t)b * HW * DQK;
    const __nv_bfloat16* Vg = g_V + (size_t)b * HW * DV;

    // prefetch KV tile 0
    {
        __nv_bfloat16* dK = sK;
        __nv_bfloat16* dV = sV;
        #pragma unroll
        for (int j = 0; j < 4; j++) {
            int u = tid + j * 256; int r = u >> 4, c8 = (u & 15) * 8;
            CP16(smem_u32(dK + r * SQ_STRIDE + c8), Kg + (size_t)r * DQK + c8);
        }
        #pragma unroll
        for (int j = 0; j < 8; j++) {
            int u = tid + j * 256; int r = u >> 5, c8 = (u & 31) * 8;
            CP16(smem_u32(dV + r * SV_STRIDE + c8), Vg + (size_t)r * DV + c8);
        }
        CP_COMMIT();
    }

    // stage Q tile (plain)
    for (int i = tid; i < 128 * 16; i += 256) {
        int r = i >> 4, d8 = (i & 15) << 3;
        *reinterpret_cast<uint4*>(sQ + r * SQ_STRIDE + d8) =
            *reinterpret_cast<const uint4*>(Qg + (size_t)(q0 + r) * DQK + d8);
    }

    float O[32][4];
    #pragma unroll
    for (int n = 0; n < 32; n++) { O[n][0] = O[n][1] = O[n][2] = O[n][3] = 0.f; }
    float m0 = -1e30f, m1 = -1e30f, l0 = 0.f, l1 = 0.f;

    const int mrow0 = warp * 16;
    const uint32_t aQbase = smem_u32(sQ + (mrow0 + (lane & 15)) * SQ_STRIDE + ((lane >> 4) & 1) * 8);
    const int krow = (lane & 7) + ((lane >> 4) & 1) * 8;
    const int kcol = ((lane >> 3) & 1) * 8;
    const int vrow = lane & 15;
    const int vsel = ((lane >> 4) & 1) * 16;   // bytes
    const float qs = 0.08838834764831845f * 1.4426950408889634f;

    for (int t = 0; t < 64; t++) {
        if (t < 63) {   // prefetch tile t+1
            int kv1 = (t + 1) * 64, s1 = (t + 1) & 1;
            __nv_bfloat16* dK = sK + s1 * 64 * SQ_STRIDE;
            __nv_bfloat16* dV = sV + s1 * 64 * SV_STRIDE;
            #pragma unroll
            for (int j = 0; j < 4; j++) {
                int u = tid + j * 256; int r = u >> 4, c8 = (u & 15) * 8;
                CP16(smem_u32(dK + r * SQ_STRIDE + c8), Kg + (size_t)(kv1 + r) * DQK + c8);
            }
            #pragma unroll
            for (int j = 0; j < 8; j++) {
                int u = tid + j * 256; int r = u >> 5, c8 = (u & 31) * 8;
                CP16(smem_u32(dV + r * SV_STRIDE + c8), Vg + (size_t)(kv1 + r) * DV + c8);
            }
            CP_COMMIT();
            CP_WAIT1();
        } else {
            CP_WAIT0();
        }
        __syncthreads();

        const int s = t & 1;
        const __nv_bfloat16* sKb = sK + s * 64 * SQ_STRIDE;
        const __nv_bfloat16* sVb = sV + s * 64 * SV_STRIDE;
        const uint32_t kbase = smem_u32(sKb + krow * SQ_STRIDE + kcol);

        // S = Q K^T
        float S[8][4];
        #pragma unroll
        for (int j = 0; j < 8; j++) { S[j][0] = S[j][1] = S[j][2] = S[j][3] = 0.f; }
        #pragma unroll
        for (int kk = 0; kk < 8; kk++) {
            uint32_t a0, a1, a2, a3;
            ldm_x4(a0, a1, a2, a3, aQbase + kk * 32);
            #pragma unroll
            for (int j2 = 0; j2 < 4; j2++) {
                uint32_t b0, b1, b2, b3;
                ldm_x4(b0, b1, b2, b3, kbase + (j2 * 16 * SQ_STRIDE + kk * 16) * 2);
                mma_bf16(S[2*j2][0],   S[2*j2][1],   S[2*j2][2],   S[2*j2][3],   a0, a1, a2, a3, b0, b1);
                mma_bf16(S[2*j2+1][0], S[2*j2+1][1], S[2*j2+1][2], S[2*j2+1][3], a0, a1, a2, a3, b2, b3);
            }
        }

        // online softmax
        float mx0 = -1e30f, mx1 = -1e30f;
        #pragma unroll
        for (int j = 0; j < 8; j++) {
            mx0 = fmaxf(mx0, fmaxf(S[j][0], S[j][1]));
            mx1 = fmaxf(mx1, fmaxf(S[j][2], S[j][3]));
        }
        mx0 = fmaxf(mx0, __shfl_xor_sync(0xffffffffu, mx0, 1));
        mx0 = fmaxf(mx0, __shfl_xor_sync(0xffffffffu, mx0, 2));
        mx1 = fmaxf(mx1, __shfl_xor_sync(0xffffffffu, mx1, 1));
        mx1 = fmaxf(mx1, __shfl_xor_sync(0xffffffffu, mx1, 2));
        mx0 *= qs; mx1 *= qs;
        const float mn0 = fmaxf(m0, mx0), mn1 = fmaxf(m1, mx1);
        const float al0 = exp2f(m0 - mn0), al1 = exp2f(m1 - mn1);
        m0 = mn0; m1 = mn1;
        float rs0 = 0.f, rs1 = 0.f;
        #pragma unroll
        for (int j = 0; j < 8; j++) {
            S[j][0] = exp2f(fmaf(S[j][0], qs, -mn0));
            S[j][1] = exp2f(fmaf(S[j][1], qs, -mn0));
            S[j][2] = exp2f(fmaf(S[j][2], qs, -mn1));
            S[j][3] = exp2f(fmaf(S[j][3], qs, -mn1));
            rs0 += S[j][0] + S[j][1];
            rs1 += S[j][2] + S[j][3];
        }
        l0 = l0 * al0 + rs0;
        l1 = l1 * al1 + rs1;
        #pragma unroll
        for (int n = 0; n < 32; n++) {
            O[n][0] *= al0; O[n][1] *= al0; O[n][2] *= al1; O[n][3] *= al1;
        }

        // O += P V
        #pragma unroll
        for (int kc = 0; kc < 4; kc++) {
            uint32_t a0 = packbf2(S[2*kc][0],   S[2*kc][1]);
            uint32_t a1 = packbf2(S[2*kc][2],   S[2*kc][3]);
            uint32_t a2 = packbf2(S[2*kc+1][0], S[2*kc+1][1]);
            uint32_t a3 = packbf2(S[2*kc+1][2], S[2*kc+1][3]);
            uint32_t vb = smem_u32(sVb + (kc * 16 + vrow) * SV_STRIDE) + vsel;
            #pragma unroll
            for (int n2 = 0; n2 < 16; n2++) {
                uint32_t b0, b1, b2, b3;
                ldm_x4t(b0, b1, b2, b3, vb + n2 * 32);
                mma_bf16(O[2*n2][0],   O[2*n2][1],   O[2*n2][2],   O[2*n2][3],   a0, a1, a2, a3, b0, b1);
                mma_bf16(O[2*n2+1][0], O[2*n2+1][1], O[2*n2+1][2], O[2*n2+1][3], a0, a1, a2, a3, b2, b3);
            }
        }
        __syncthreads();
    }

    // finalize: divide by l, write H (bf16)
    l0 += __shfl_xor_sync(0xffffffffu, l0, 1);
    l0 += __shfl_xor_sync(0xffffffffu, l0, 2);
    l1 += __shfl_xor_sync(0xffffffffu, l1, 1);
    l1 += __shfl_xor_sync(0xffffffffu, l1, 2);
    const float inv0 = 1.f / l0, inv1 = 1.f / l1;
    const int r0 = q0 + mrow0 + (lane >> 2);
    uint32_t* H0 = reinterpret_cast<uint32_t*>(g_Hb + ((size_t)b * HW + r0) * DV) + (lane & 3);
    uint32_t* H1 = H0 + 8 * (DV / 2);
    #pragma unroll
    for (int n = 0; n < 32; n++) {
        H0[n * 4] = packbf2(O[n][0] * inv0, O[n][1] * inv0);
        H1[n * 4] = packbf2(O[n][2] * inv1, O[n][3] * inv1);
    }
}

// ---------------- output GEMM + residual (tensor cores) ----------------
// C[f][n] = sum_e Wo[f][e] H[n][e]; m = f (256), n = spatial (64/CTA), K = 256 chunked by 64.
#define OSTR 72
#define OUT_SMEM ((256 * OSTR + 64 * OSTR) * 2)   // 46080 B

__global__ __launch_bounds__(256) void out_mma_kernel(
        const float* __restrict__ x, const float* __restrict__ bo, float* __restrict__ out) {
    extern __shared__ __nv_bfloat16 osmem[];
    __nv_bfloat16* sW = osmem;                 // [256][72]
    __nv_bfloat16* sH = osmem + 256 * OSTR;    // [64][72]
    const int b = blockIdx.y, n0 = blockIdx.x * 64;
    const int tid = threadIdx.x, warp = tid >> 5, lane = tid & 31;

    const __nv_bfloat16* Hb = g_Hb + ((size_t)b * HW + n0) * DV;

    float acc[2][8][4];
    #pragma unroll
    for (int mt = 0; mt < 2; mt++)
        #pragma unroll
        for (int nt = 0; nt < 8; nt++) { acc[mt][nt][0] = acc[mt][nt][1] = acc[mt][nt][2] = acc[mt][nt][3] = 0.f; }

    const int arow = lane & 15;
    const int acol = ((lane >> 4) & 1) * 8;
    const uint32_t aBase = smem_u32(sW + (warp * 32 + arow) * OSTR + acol);
    const int brow = (lane & 7) + ((lane >> 4) & 1) * 8;
    const int bcol = ((lane >> 3) & 1) * 8;
    const uint32_t bBase = smem_u32(sH + brow * OSTR + bcol);

    for (int ck = 0; ck < 4; ck++) {
        __syncthreads();
        #pragma unroll
        for (int j = 0; j < 8; j++) {
            int u = tid + j * 256;              // 0..2047
            int r = u >> 3, c8 = (u & 7) * 8;
            *reinterpret_cast<uint4*>(sW + r * OSTR + c8) =
                *reinterpret_cast<const uint4*>(g_Wob + (size_t)r * 256 + ck * 64 + c8);
        }
        #pragma unroll
        for (int j = 0; j < 2; j++) {
            int u = tid + j * 256;              // 0..511
            int r = u >> 3, c8 = (u & 7) * 8;
            *reinterpret_cast<uint4*>(sH + r * OSTR + c8) =
                *reinterpret_cast<const uint4*>(Hb + (size_t)r * DV + ck * 64 + c8);
        }
        __syncthreads();

        #pragma unroll
        for (int kk = 0; kk < 4; kk++) {
            uint32_t bf[4][4];
            #pragma unroll
            for (int p = 0; p < 4; p++)
                ldm_x4(bf[p][0], bf[p][1], bf[p][2], bf[p][3], bBase + (p * 16 * OSTR + kk * 16) * 2);
            #pragma unroll
            for (int mt = 0; mt < 2; mt++) {
                uint32_t a0, a1, a2, a3;
                ldm_x4(a0, a1, a2, a3, aBase + (mt * 16 * OSTR + kk * 16) * 2);
                #pragma unroll
                for (int p = 0; p < 4; p++) {
                    mma_bf16(acc[mt][2*p][0],   acc[mt][2*p][1],   acc[mt][2*p][2],   acc[mt][2*p][3],   a0, a1, a2, a3, bf[p][0], bf[p][1]);
                    mma_bf16(acc[mt][2*p+1][0], acc[mt][2*p+1][1], acc[mt][2*p+1][2], acc[mt][2*p+1][3], a0, a1, a2, a3, bf[p][2], bf[p][3]);
                }
            }
        }
    }

    // epilogue: residual + bias, direct [b][f][n] stores
    #pragma unroll
    for (int mt = 0; mt < 2; mt++) {
        int f = warp * 32 + mt * 16 + (lane >> 2);
        float bias0 = bo[f], bias1 = bo[f + 8];
        #pragma unroll
        for (int nt = 0; nt < 8; nt++) {
            int n = n0 + nt * 8 + (lane & 3) * 2;
            size_t i0 = ((size_t)(b * 256 + f)) * HW + n;
            float2 xv0 = *reinterpret_cast<const float2*>(x + i0);
            float2 ov0 = make_float2(xv0.x + acc[mt][nt][0] + bias0, xv0.y + acc[mt][nt][1] + bias0);
            *reinterpret_cast<float2*>(out + i0) = ov0;
            size_t i1 = i0 + (size_t)8 * HW;
            float2 xv1 = *reinterpret_cast<const float2*>(x + i1);
            float2 ov1 = make_float2(xv1.x + acc[mt][nt][2] + bias1, xv1.y + acc[mt][nt][3] + bias1);
            *reinterpret_cast<float2*>(out + i1) = ov1;
        }
    }
}

// ---------------- launch ----------------
extern "C" void kernel_launch(void* const* d_in, const int* in_sizes, int n_in,
                              void* d_out, int out_size) {
    const float* x  = (const float*)d_in[0];
    const float* y  = (const float*)d_in[1];
    const float* Wq = (const float*)d_in[2];
    const float* bq = (const float*)d_in[3];
    const float* Wk = (const float*)d_in[4];
    const float* bk = (const float*)d_in[5];
    const float* Wv = (const float*)d_in[6];
    const float* bv = (const float*)d_in[7];
    const float* Wo = (const float*)d_in[8];
    const float* bo = (const float*)d_in[9];
    float* out = (float*)d_out;

    __nv_bfloat16 *dXb, *dYb, *dWqkv, *dWob;
    cudaGetSymbolAddress((void**)&dXb, g_Xb);
    cudaGetSymbolAddress((void**)&dYb, g_Yb);
    cudaGetSymbolAddress((void**)&dWqkv, g_Wqkv);
    cudaGetSymbolAddress((void**)&dWob, g_Wob);

    const int NX = BATCH * CIN * HW;   // 8388608
    cvt_kernel<<<NX / 1024, 256>>>(x, dXb, NX);
    cvt_kernel<<<NX / 1024, 256>>>(y, dYb, NX);
    cvt_kernel<<<32, 256>>>(Wq, dWqkv, 128 * 256);
    cvt_kernel<<<32, 256>>>(Wk, dWqkv + 128 * 256, 128 * 256);
    cvt_kernel<<<64, 256>>>(Wv, dWqkv + 256 * 256, 256 * 256);
    cvt_kernel<<<64, 256>>>(Wo, dWob, 256 * 256);

    cudaFuncSetAttribute(proj_mma_kernel, cudaFuncAttributeMaxDynamicSharedMemorySize, PROJ_SMEM);
    proj_mma_kernel<<<dim3(HW / 64, BATCH), 256, PROJ_SMEM>>>(bq, bk, bv);

    cudaFuncSetAttribute(flash_kernel, cudaFuncAttributeMaxDynamicSharedMemorySize, FLASH_SMEM);
    flash_kernel<<<dim3(HW / 128, BATCH), 256, FLASH_SMEM>>>();

    cudaFuncSetAttribute(out_mma_kernel, cudaFuncAttributeMaxDynamicSharedMemorySize, OUT_SMEM);
    out_mma_kernel<<<dim3(HW / 64, BATCH), 256, OUT_SMEM>>>(x, bo, out);
}

// round 3
// speedup vs baseline: 2.5433x; 1.0016x over previous
#include <cuda_runtime.h>
#include <cuda_bf16.h>
#include <cstdint>

#define BATCH 8
#define HW    4096
#define CIN   256
#define DQK   128
#define DV    256

// ---------------- scratch (static __device__, no allocs) ----------------
__device__ __nv_bfloat16 g_Xb[(size_t)BATCH * CIN * HW];     // x in bf16, [b][c][n]
__device__ __nv_bfloat16 g_Yb[(size_t)BATCH * CIN * HW];     // y in bf16
__device__ __nv_bfloat16 g_Wqkv[512 * 256];                  // rows 0-127 Wq, 128-255 Wk, 256-511 Wv
__device__ __nv_bfloat16 g_Wob[256 * 256];                   // Wo bf16
__device__ __nv_bfloat16 g_Q[(size_t)BATCH * HW * DQK];      // [b][n][d]
__device__ __nv_bfloat16 g_K[(size_t)BATCH * HW * DQK];      // [b][n][d]
__device__ __nv_bfloat16 g_V[(size_t)BATCH * HW * DV];       // [b][n][e]
__device__ __nv_bfloat16 g_Hb[(size_t)BATCH * HW * DV];      // attention output, bf16

// ---------------- helpers ----------------
__device__ __forceinline__ uint32_t smem_u32(const void* p) {
    return (uint32_t)__cvta_generic_to_shared(p);
}
__device__ __forceinline__ void ldm_x4(uint32_t& r0, uint32_t& r1, uint32_t& r2, uint32_t& r3, uint32_t addr) {
    asm volatile("ldmatrix.sync.aligned.m8n8.x4.shared.b16 {%0,%1,%2,%3},[%4];"
                 : "=r"(r0), "=r"(r1), "=r"(r2), "=r"(r3) : "r"(addr));
}
__device__ __forceinline__ void ldm_x4t(uint32_t& r0, uint32_t& r1, uint32_t& r2, uint32_t& r3, uint32_t addr) {
    asm volatile("ldmatrix.sync.aligned.m8n8.x4.trans.shared.b16 {%0,%1,%2,%3},[%4];"
                 : "=r"(r0), "=r"(r1), "=r"(r2), "=r"(r3) : "r"(addr));
}
__device__ __forceinline__ void mma_bf16(float& c0, float& c1, float& c2, float& c3,
                                         uint32_t a0, uint32_t a1, uint32_t a2, uint32_t a3,
                                         uint32_t b0, uint32_t b1) {
    asm volatile("mma.sync.aligned.m16n8k16.row.col.f32.bf16.bf16.f32 "
                 "{%0,%1,%2,%3},{%4,%5,%6,%7},{%8,%9},{%0,%1,%2,%3};"
                 : "+f"(c0), "+f"(c1), "+f"(c2), "+f"(c3)
                 : "r"(a0), "r"(a1), "r"(a2), "r"(a3), "r"(b0), "r"(b1));
}
__device__ __forceinline__ uint32_t packbf2(float lo, float hi) {
    __nv_bfloat162 v = __floats2bfloat162_rn(lo, hi);
    return *reinterpret_cast<uint32_t*>(&v);
}
#define CP16(saddr, gptr) \
    asm volatile("cp.async.cg.shared.global [%0],[%1],16;" :: "r"(saddr), "l"(gptr))
#define CP_COMMIT() asm volatile("cp.async.commit_group;")
#define CP_WAIT1()  asm volatile("cp.async.wait_group 1;")
#define CP_WAIT0()  asm volatile("cp.async.wait_group 0;")

// ---------------- prep: fp32 -> bf16 conversion ----------------
__global__ __launch_bounds__(256) void cvt_kernel(const float* __restrict__ src,
                                                  __nv_bfloat16* __restrict__ dst, int n) {
    int i = (blockIdx.x * 256 + threadIdx.x) * 4;
    if (i < n) {
        float4 v = *reinterpret_cast<const float4*>(src + i);
        uint2 o;
        o.x = packbf2(v.x, v.y);
        o.y = packbf2(v.z, v.w);
        *reinterpret_cast<uint2*>(dst + i) = o;
    }
}

// ---------------- projection GEMM (tensor cores) ----------------
// Per CTA: 64 spatial rows x 512 outputs, K=256 chunked by 64.
// 8 warps = 4 (m-groups of 16 rows) x 2 (output halves of 256).
#define PSTR 72
#define PROJ_SMEM ((128 * PSTR + 512 * PSTR) * 2)   // sX+sY + sW = 92160 B

__global__ __launch_bounds__(256, 1) void proj_mma_kernel(
        const float* __restrict__ bq, const float* __restrict__ bk, const float* __restrict__ bv) {
    extern __shared__ __nv_bfloat16 psmem[];
    __nv_bfloat16* sX = psmem;                 // [64][72]
    __nv_bfloat16* sY = psmem + 64 * PSTR;     // [64][72]
    __nv_bfloat16* sW = psmem + 128 * PSTR;    // [512][72]
    __shared__ float sBias[512];

    const int b = blockIdx.y, n0 = blockIdx.x * 64;
    const int tid = threadIdx.x, warp = tid >> 5, lane = tid & 31;
    const int mg = warp & 3, dg = warp >> 2;

    for (int i = tid; i < 512; i += 256)
        sBias[i] = (i < 128) ? bq[i] : (i < 256) ? bk[i - 128] : bv[i - 256];

    const __nv_bfloat16* Xb = g_Xb + (size_t)b * CIN * HW + n0;
    const __nv_bfloat16* Yb = g_Yb + (size_t)b * CIN * HW + n0;

    float acc[32][4];
    #pragma unroll
    for (int t = 0; t < 32; t++) { acc[t][0] = acc[t][1] = acc[t][2] = acc[t][3] = 0.f; }

    // A (trans) addressing: row = k-within-chunk, col = m
    const int arow = (lane & 7) + ((lane >> 4) & 1) * 8;
    const int acol = mg * 16 + ((lane >> 3) & 1) * 8;
    const uint32_t aXbase = smem_u32(sX + arow * PSTR + acol);
    const uint32_t aYbase = smem_u32(sY + arow * PSTR + acol);
    // B addressing: row = output d, col = k-within-chunk
    const int brow = (lane & 7) + ((lane >> 4) & 1) * 8;
    const int bcol = ((lane >> 3) & 1) * 8;
    const uint32_t bWbase = smem_u32(sW + (dg * 256 + brow) * PSTR + bcol);

    for (int ck = 0; ck < 4; ck++) {
        __syncthreads();
        #pragma unroll
        for (int j = 0; j < 4; j++) {
            int u = tid + j * 256;              // 0..1023
            int r = u >> 3, c8 = (u & 7) * 8;
            *reinterpret_cast<uint4*>(sX + r * PSTR + c8) =
                *reinterpret_cast<const uint4*>(Xb + (size_t)(ck * 64 + r) * HW + c8);
            *reinterpret_cast<uint4*>(sY + r * PSTR + c8) =
                *reinterpret_cast<const uint4*>(Yb + (size_t)(ck * 64 + r) * HW + c8);
        }
        #pragma unroll
        for (int j = 0; j < 16; j++) {
            int u = tid + j * 256;              // 0..4095
            int r = u >> 3, c8 = (u & 7) * 8;
            *reinterpret_cast<uint4*>(sW + r * PSTR + c8) =
                *reinterpret_cast<const uint4*>(g_Wqkv + (size_t)r * 256 + ck * 64 + c8);
        }
        __syncthreads();

        #pragma unroll
        for (int kk = 0; kk < 4; kk++) {
            uint32_t ax0, ax1, ax2, ax3;
            ldm_x4t(ax0, ax1, ax2, ax3, aXbase + kk * 16 * PSTR * 2);
            uint32_t ay0 = ax0, ay1 = ax1, ay2 = ax2, ay3 = ax3;
            if (dg == 0) ldm_x4t(ay0, ay1, ay2, ay3, aYbase + kk * 16 * PSTR * 2);
            #pragma unroll
            for (int t2 = 0; t2 < 16; t2++) {
                uint32_t b0, b1, b2, b3;
                ldm_x4(b0, b1, b2, b3, bWbase + (t2 * 16 * PSTR + kk * 16) * 2);
                if (dg == 0 && t2 < 8) {   // Q tiles use Y
                    mma_bf16(acc[2*t2][0],   acc[2*t2][1],   acc[2*t2][2],   acc[2*t2][3],   ay0, ay1, ay2, ay3, b0, b1);
                    mma_bf16(acc[2*t2+1][0], acc[2*t2+1][1], acc[2*t2+1][2], acc[2*t2+1][3], ay0, ay1, ay2, ay3, b2, b3);
                } else {                    // K,V tiles use X
                    mma_bf16(acc[2*t2][0],   acc[2*t2][1],   acc[2*t2][2],   acc[2*t2][3],   ax0, ax1, ax2, ax3, b0, b1);
                    mma_bf16(acc[2*t2+1][0], acc[2*t2+1][1], acc[2*t2+1][2], acc[2*t2+1][3], ax0, ax1, ax2, ax3, b2, b3);
                }
            }
        }
    }

    // epilogue: bias + pack bf16 + store to Q/K/V
    const int r = n0 + mg * 16 + (lane >> 2);
    const int cpair = (lane & 3) * 2;
    #pragma unroll
    for (int t = 0; t < 32; t++) {
        int d0 = dg * 256 + t * 8 + cpair;
        float bv0 = sBias[d0], bv1 = sBias[d0 + 1];
        uint32_t v0 = packbf2(acc[t][0] + bv0, acc[t][1] + bv1);
        uint32_t v1 = packbf2(acc[t][2] + bv0, acc[t][3] + bv1);
        __nv_bfloat16* dst; int ld, stride;
        if (d0 < 128)      { dst = g_Q; ld = d0;       stride = DQK; }
        else if (d0 < 256) { dst = g_K; ld = d0 - 128; stride = DQK; }
        else               { dst = g_V; ld = d0 - 256; stride = DV;  }
        *reinterpret_cast<uint32_t*>(dst + ((size_t)b * HW + r) * stride + ld) = v0;
        *reinterpret_cast<uint32_t*>(dst + ((size_t)b * HW + r + 8) * stride + ld) = v1;
    }
}

// ---------------- flash attention (mma.sync bf16, cp.async pipelined) ----------------
#define SQ_STRIDE 136
#define SV_STRIDE 264
#define FLASH_SMEM ((128 * SQ_STRIDE + 2 * 64 * SQ_STRIDE + 2 * 64 * SV_STRIDE) * 2)  // 137216

__global__ __launch_bounds__(256, 1) void flash_kernel() {
    extern __shared__ __nv_bfloat16 smem[];
    __nv_bfloat16* sQ = smem;
    __nv_bfloat16* sK = smem + 128 * SQ_STRIDE;
    __nv_bfloat16* sV = smem + 128 * SQ_STRIDE + 2 * 64 * SQ_STRIDE;

    const int b = blockIdx.y;
    const int q0 = blockIdx.x * 128;
    const int tid = threadIdx.x, warp = tid >> 5, lane = tid & 31;
    const __nv_bfloat16* Qg = g_Q + (size_t)b * HW * DQK;
    const __nv_bfloat16* Kg = g_K + (size_t)b * HW * DQK;
    const __nv_bfloat16* Vg = g_V + (size_t)b * HW * DV;

    // prefetch KV tile 0
    {
        __nv_bfloat16* dK = sK;
        __nv_bfloat16* dV = sV;
        #pragma unroll
        for (int j = 0; j < 4; j++) {
            int u = tid + j * 256; int r = u >> 4, c8 = (u & 15) * 8;
            CP16(smem_u32(dK + r * SQ_STRIDE + c8), Kg + (size_t)r * DQK + c8);
        }
        #pragma unroll
        for (int j = 0; j < 8; j++) {
            int u = tid + j * 256; int r = u >> 5, c8 = (u & 31) * 8;
            CP16(smem_u32(dV + r * SV_STRIDE + c8), Vg + (size_t)r * DV + c8);
        }
        CP_COMMIT();
    }

    // stage Q tile (plain)
    for (int i = tid; i < 128 * 16; i += 256) {
        int r = i >> 4, d8 = (i & 15) << 3;
        *reinterpret_cast<uint4*>(sQ + r * SQ_STRIDE + d8) =
            *reinterpret_cast<const uint4*>(Qg + (size_t)(q0 + r) * DQK + d8);
    }

    float O[32][4];
    #pragma unroll
    for (int n = 0; n < 32; n++) { O[n][0] = O[n][1] = O[n][2] = O[n][3] = 0.f; }
    float m0 = -1e30f, m1 = -1e30f, l0 = 0.f, l1 = 0.f;

    const int mrow0 = warp * 16;
    const uint32_t aQbase = smem_u32(sQ + (mrow0 + (lane & 15)) * SQ_STRIDE + ((lane >> 4) & 1) * 8);
    const int krow = (lane & 7) + ((lane >> 4) & 1) * 8;
    const int kcol = ((lane >> 3) & 1) * 8;
    const int vrow = lane & 15;
    const int vsel = ((lane >> 4) & 1) * 16;   // bytes
    const float qs = 0.08838834764831845f * 1.4426950408889634f;

    for (int t = 0; t < 64; t++) {
        if (t < 63) {   // prefetch tile t+1
            int kv1 = (t + 1) * 64, s1 = (t + 1) & 1;
            __nv_bfloat16* dK = sK + s1 * 64 * SQ_STRIDE;
            __nv_bfloat16* dV = sV + s1 * 64 * SV_STRIDE;
            #pragma unroll
            for (int j = 0; j < 4; j++) {
                int u = tid + j * 256; int r = u >> 4, c8 = (u & 15) * 8;
                CP16(smem_u32(dK + r * SQ_STRIDE + c8), Kg + (size_t)(kv1 + r) * DQK + c8);
            }
            #pragma unroll
            for (int j = 0; j < 8; j++) {
                int u = tid + j * 256; int r = u >> 5, c8 = (u & 31) * 8;
                CP16(smem_u32(dV + r * SV_STRIDE + c8), Vg + (size_t)(kv1 + r) * DV + c8);
            }
            CP_COMMIT();
            CP_WAIT1();
        } else {
            CP_WAIT0();
        }
        __syncthreads();

        const int s = t & 1;
        const __nv_bfloat16* sKb = sK + s * 64 * SQ_STRIDE;
        const __nv_bfloat16* sVb = sV + s * 64 * SV_STRIDE;
        const uint32_t kbase = smem_u32(sKb + krow * SQ_STRIDE + kcol);

        // S = Q K^T
        float S[8][4];
        #pragma unroll
        for (int j = 0; j < 8; j++) { S[j][0] = S[j][1] = S[j][2] = S[j][3] = 0.f; }
        #pragma unroll
        for (int kk = 0; kk < 8; kk++) {
            uint32_t a0, a1, a2, a3;
            ldm_x4(a0, a1, a2, a3, aQbase + kk * 32);
            #pragma unroll
            for (int j2 = 0; j2 < 4; j2++) {
                uint32_t b0, b1, b2, b3;
                ldm_x4(b0, b1, b2, b3, kbase + (j2 * 16 * SQ_STRIDE + kk * 16) * 2);
                mma_bf16(S[2*j2][0],   S[2*j2][1],   S[2*j2][2],   S[2*j2][3],   a0, a1, a2, a3, b0, b1);
                mma_bf16(S[2*j2+1][0], S[2*j2+1][1], S[2*j2+1][2], S[2*j2+1][3], a0, a1, a2, a3, b2, b3);
            }
        }

        // online softmax
        float mx0 = -1e30f, mx1 = -1e30f;
        #pragma unroll
        for (int j = 0; j < 8; j++) {
            mx0 = fmaxf(mx0, fmaxf(S[j][0], S[j][1]));
            mx1 = fmaxf(mx1, fmaxf(S[j][2], S[j][3]));
        }
        mx0 = fmaxf(mx0, __shfl_xor_sync(0xffffffffu, mx0, 1));
        mx0 = fmaxf(mx0, __shfl_xor_sync(0xffffffffu, mx0, 2));
        mx1 = fmaxf(mx1, __shfl_xor_sync(0xffffffffu, mx1, 1));
        mx1 = fmaxf(mx1, __shfl_xor_sync(0xffffffffu, mx1, 2));
        mx0 *= qs; mx1 *= qs;
        const float mn0 = fmaxf(m0, mx0), mn1 = fmaxf(m1, mx1);
        const float al0 = exp2f(m0 - mn0), al1 = exp2f(m1 - mn1);
        m0 = mn0; m1 = mn1;
        float rs0 = 0.f, rs1 = 0.f;
        #pragma unroll
        for (int j = 0; j < 8; j++) {
            S[j][0] = exp2f(fmaf(S[j][0], qs, -mn0));
            S[j][1] = exp2f(fmaf(S[j][1], qs, -mn0));
            S[j][2] = exp2f(fmaf(S[j][2], qs, -mn1));
            S[j][3] = exp2f(fmaf(S[j][3], qs, -mn1));
            rs0 += S[j][0] + S[j][1];
            rs1 += S[j][2] + S[j][3];
        }
        l0 = l0 * al0 + rs0;
        l1 = l1 * al1 + rs1;
        #pragma unroll
        for (int n = 0; n < 32; n++) {
            O[n][0] *= al0; O[n][1] *= al0; O[n][2] *= al1; O[n][3] *= al1;
        }

        // O += P V
        #pragma unroll
        for (int kc = 0; kc < 4; kc++) {
            uint32_t a0 = packbf2(S[2*kc][0],   S[2*kc][1]);
            uint32_t a1 = packbf2(S[2*kc][2],   S[2*kc][3]);
            uint32_t a2 = packbf2(S[2*kc+1][0], S[2*kc+1][1]);
            uint32_t a3 = packbf2(S[2*kc+1][2], S[2*kc+1][3]);
            uint32_t vb = smem_u32(sVb + (kc * 16 + vrow) * SV_STRIDE) + vsel;
            #pragma unroll
            for (int n2 = 0; n2 < 16; n2++) {
                uint32_t b0, b1, b2, b3;
                ldm_x4t(b0, b1, b2, b3, vb + n2 * 32);
                mma_bf16(O[2*n2][0],   O[2*n2][1],   O[2*n2][2],   O[2*n2][3],   a0, a1, a2, a3, b0, b1);
                mma_bf16(O[2*n2+1][0], O[2*n2+1][1], O[2*n2+1][2], O[2*n2+1][3], a0, a1, a2, a3, b2, b3);
            }
        }
        __syncthreads();
    }

    // finalize: divide by l, write H (bf16)
    l0 += __shfl_xor_sync(0xffffffffu, l0, 1);
    l0 += __shfl_xor_sync(0xffffffffu, l0, 2);
    l1 += __shfl_xor_sync(0xffffffffu, l1, 1);
    l1 += __shfl_xor_sync(0xffffffffu, l1, 2);
    const float inv0 = 1.f / l0, inv1 = 1.f / l1;
    const int r0 = q0 + mrow0 + (lane >> 2);
    uint32_t* H0 = reinterpret_cast<uint32_t*>(g_Hb + ((size_t)b * HW + r0) * DV) + (lane & 3);
    uint32_t* H1 = H0 + 8 * (DV / 2);
    #pragma unroll
    for (int n = 0; n < 32; n++) {
        H0[n * 4] = packbf2(O[n][0] * inv0, O[n][1] * inv0);
        H1[n * 4] = packbf2(O[n][2] * inv1, O[n][3] * inv1);
    }
}

// ---------------- output GEMM + residual (tensor cores) ----------------
// C[f][n] = sum_e Wo[f][e] H[n][e]; m = f (256), n = spatial (64/CTA), K = 256 chunked by 64.
#define OSTR 72
#define OUT_SMEM ((256 * OSTR + 64 * OSTR) * 2)   // 46080 B

__global__ __launch_bounds__(256) void out_mma_kernel(
        const float* __restrict__ x, const float* __restrict__ bo, float* __restrict__ out) {
    extern __shared__ __nv_bfloat16 osmem[];
    __nv_bfloat16* sW = osmem;                 // [256][72]
    __nv_bfloat16* sH = osmem + 256 * OSTR;    // [64][72]
    const int b = blockIdx.y, n0 = blockIdx.x * 64;
    const int tid = threadIdx.x, warp = tid >> 5, lane = tid & 31;

    const __nv_bfloat16* Hb = g_Hb + ((size_t)b * HW + n0) * DV;

    float acc[2][8][4];
    #pragma unroll
    for (int mt = 0; mt < 2; mt++)
        #pragma unroll
        for (int nt = 0; nt < 8; nt++) { acc[mt][nt][0] = acc[mt][nt][1] = acc[mt][nt][2] = acc[mt][nt][3] = 0.f; }

    const int arow = lane & 15;
    const int acol = ((lane >> 4) & 1) * 8;
    const uint32_t aBase = smem_u32(sW + (warp * 32 + arow) * OSTR + acol);
    const int brow = (lane & 7) + ((lane >> 4) & 1) * 8;
    const int bcol = ((lane >> 3) & 1) * 8;
    const uint32_t bBase = smem_u32(sH + brow * OSTR + bcol);

    for (int ck = 0; ck < 4; ck++) {
        __syncthreads();
        #pragma unroll
        for (int j = 0; j < 8; j++) {
            int u = tid + j * 256;              // 0..2047
            int r = u >> 3, c8 = (u & 7) * 8;
            *reinterpret_cast<uint4*>(sW + r * OSTR + c8) =
                *reinterpret_cast<const uint4*>(g_Wob + (size_t)r * 256 + ck * 64 + c8);
        }
        #pragma unroll
        for (int j = 0; j < 2; j++) {
            int u = tid + j * 256;              // 0..511
            int r = u >> 3, c8 = (u & 7) * 8;
            *reinterpret_cast<uint4*>(sH + r * OSTR + c8) =
                *reinterpret_cast<const uint4*>(Hb + (size_t)r * DV + ck * 64 + c8);
        }
        __syncthreads();

        #pragma unroll
        for (int kk = 0; kk < 4; kk++) {
            uint32_t bf[4][4];
            #pragma unroll
            for (int p = 0; p < 4; p++)
                ldm_x4(bf[p][0], bf[p][1], bf[p][2], bf[p][3], bBase + (p * 16 * OSTR + kk * 16) * 2);
            #pragma unroll
            for (int mt = 0; mt < 2; mt++) {
                uint32_t a0, a1, a2, a3;
                ldm_x4(a0, a1, a2, a3, aBase + (mt * 16 * OSTR + kk * 16) * 2);
                #pragma unroll
                for (int p = 0; p < 4; p++) {
                    mma_bf16(acc[mt][2*p][0],   acc[mt][2*p][1],   acc[mt][2*p][2],   acc[mt][2*p][3],   a0, a1, a2, a3, bf[p][0], bf[p][1]);
                    mma_bf16(acc[mt][2*p+1][0], acc[mt][2*p+1][1], acc[mt][2*p+1][2], acc[mt][2*p+1][3], a0, a1, a2, a3, bf[p][2], bf[p][3]);
                }
            }
        }
    }

    // epilogue: residual + bias, direct [b][f][n] stores
    #pragma unroll
    for (int mt = 0; mt < 2; mt++) {
        int f = warp * 32 + mt * 16 + (lane >> 2);
        float bias0 = bo[f], bias1 = bo[f + 8];
        #pragma unroll
        for (int nt = 0; nt < 8; nt++) {
            int n = n0 + nt * 8 + (lane & 3) * 2;
            size_t i0 = ((size_t)(b * 256 + f)) * HW + n;
            float2 xv0 = *reinterpret_cast<const float2*>(x + i0);
            float2 ov0 = make_float2(xv0.x + acc[mt][nt][0] + bias0, xv0.y + acc[mt][nt][1] + bias0);
            *reinterpret_cast<float2*>(out + i0) = ov0;
            size_t i1 = i0 + (size_t)8 * HW;
            float2 xv1 = *reinterpret_cast<const float2*>(x + i1);
            float2 ov1 = make_float2(xv1.x + acc[mt][nt][2] + bias1, xv1.y + acc[mt][nt][3] + bias1);
            *reinterpret_cast<float2*>(out + i1) = ov1;
        }
    }
}

// ---------------- launch ----------------
extern "C" void kernel_launch(void* const* d_in, const int* in_sizes, int n_in,
                              void* d_out, int out_size) {
    const float* x  = (const float*)d_in[0];
    const float* y  = (const float*)d_in[1];
    const float* Wq = (const float*)d_in[2];
    const float* bq = (const float*)d_in[3];
    const float* Wk = (const float*)d_in[4];
    const float* bk = (const float*)d_in[5];
    const float* Wv = (const float*)d_in[6];
    const float* bv = (const float*)d_in[7];
    const float* Wo = (const float*)d_in[8];
    const float* bo = (const float*)d_in[9];
    float* out = (float*)d_out;

    __nv_bfloat16 *dXb, *dYb, *dWqkv, *dWob;
    cudaGetSymbolAddress((void**)&dXb, g_Xb);
    cudaGetSymbolAddress((void**)&dYb, g_Yb);
    cudaGetSymbolAddress((void**)&dWqkv, g_Wqkv);
    cudaGetSymbolAddress((void**)&dWob, g_Wob);

    const int NX = BATCH * CIN * HW;   // 8388608
    cvt_kernel<<<NX / 1024, 256>>>(x, dXb, NX);
    cvt_kernel<<<NX / 1024, 256>>>(y, dYb, NX);
    cvt_kernel<<<32, 256>>>(Wq, dWqkv, 128 * 256);
    cvt_kernel<<<32, 256>>>(Wk, dWqkv + 128 * 256, 128 * 256);
    cvt_kernel<<<64, 256>>>(Wv, dWqkv + 256 * 256, 256 * 256);
    cvt_kernel<<<64, 256>>>(Wo, dWob, 256 * 256);

    cudaFuncSetAttribute(proj_mma_kernel, cudaFuncAttributeMaxDynamicSharedMemorySize, PROJ_SMEM);
    proj_mma_kernel<<<dim3(HW / 64, BATCH), 256, PROJ_SMEM>>>(bq, bk, bv);

    cudaFuncSetAttribute(flash_kernel, cudaFuncAttributeMaxDynamicSharedMemorySize, FLASH_SMEM);
    flash_kernel<<<dim3(HW / 128, BATCH), 256, FLASH_SMEM>>>();

    cudaFuncSetAttribute(out_mma_kernel, cudaFuncAttributeMaxDynamicSharedMemorySize, OUT_SMEM);
    out_mma_kernel<<<dim3(HW / 64, BATCH), 256, OUT_SMEM>>>(x, bo, out);
}